// round 13
// baseline (speedup 1.0000x reference)
#include <cuda_runtime.h>
#include <cuda_fp16.h>
#include <cstdint>

#define T_STEPS 512
#define BATCH   256
#define NH      512
#define NH2     256
#define NU      32
#define NY      64
#define TTI     16
#define NTIL    32

__device__ __half g_Xf[(size_t)(T_STEPS + 1) * BATCH * NH];
__device__ __half g_W[NY * NH];
__device__ int g_dummy_sink;

// ===================== helpers =====================
__device__ __forceinline__ uint32_t smem_u32(const void* p) {
    uint32_t a;
    asm("{ .reg .u64 t; cvta.to.shared.u64 t, %1; cvt.u32.u64 %0, t; }" : "=r"(a) : "l"(p));
    return a;
}
__device__ __forceinline__ unsigned long long pack2(float lo, float hi) {
    unsigned long long r;
    asm("mov.b64 %0, {%1, %2};" : "=l"(r) : "f"(lo), "f"(hi));
    return r;
}
__device__ __forceinline__ void unpack2(unsigned long long v, float& lo, float& hi) {
    asm("mov.b64 {%0, %1}, %2;" : "=f"(lo), "=f"(hi) : "l"(v));
}
__device__ __forceinline__ unsigned long long fma2(unsigned long long a,
                                                   unsigned long long b,
                                                   unsigned long long c) {
    unsigned long long d;
    asm("fma.rn.f32x2 %0, %1, %2, %3;" : "=l"(d) : "l"(a), "l"(b), "l"(c));
    return d;
}
__device__ __forceinline__ unsigned long long dup2(float v) { return pack2(v, v); }

__device__ __forceinline__ void split2h(float x, float y, uint32_t& h, uint32_t& l) {
    __half2 hh = __floats2half2_rn(x, y);
    h = *(uint32_t*)&hh;
    float xh = __half2float(__low2half(hh));
    float yh = __half2float(__high2half(hh));
    __half2 ll = __floats2half2_rn(x - xh, y - yh);
    l = *(uint32_t*)&ll;
}
__device__ __forceinline__ void store_f16(float xr, float xi, size_t o) {
    __half2 v = __floats2half2_rn(xr, xi);
    *(__half2*)&g_Xf[o] = v;
}
__device__ __forceinline__ void cpa16(uint32_t dst, const void* src) {
    asm volatile("cp.async.cg.shared.global [%0], [%1], 16;" :: "r"(dst), "l"(src));
}
__device__ __forceinline__ void cp_commit() {
    asm volatile("cp.async.commit_group;" ::: "memory");
}
template <int N>
__device__ __forceinline__ void cp_wait() {
    asm volatile("cp.async.wait_group %0;" :: "n"(N) : "memory");
}
__device__ __forceinline__ void ldsm4(uint32_t& r0, uint32_t& r1, uint32_t& r2, uint32_t& r3,
                                      uint32_t addr) {
    asm volatile("ldmatrix.sync.aligned.m8n8.x4.shared.b16 {%0,%1,%2,%3}, [%4];"
                 : "=r"(r0), "=r"(r1), "=r"(r2), "=r"(r3) : "r"(addr));
}
__device__ __forceinline__ void mma16816h(float* c, const uint32_t* a, const uint32_t* b) {
    asm volatile(
        "mma.sync.aligned.m16n8k16.row.col.f32.f16.f16.f32 "
        "{%0,%1,%2,%3}, {%4,%5,%6,%7}, {%8,%9}, {%0,%1,%2,%3};"
        : "+f"(c[0]), "+f"(c[1]), "+f"(c[2]), "+f"(c[3])
        : "r"(a[0]), "r"(a[1]), "r"(a[2]), "r"(a[3]), "r"(b[0]), "r"(b[1]));
}
#define NBAR_SYNC(id, n)   asm volatile("bar.sync %0, %1;"   :: "r"(id), "r"(n) : "memory")
#define NBAR_ARRIVE(id, n) asm volatile("bar.arrive %0, %1;" :: "r"(id), "r"(n) : "memory")

__global__ void k0_wsplit(const float* __restrict__ Wxy) {
    for (int i = blockIdx.x * blockDim.x + threadIdx.x; i < NY * NH2;
         i += gridDim.x * blockDim.x) {
        int n  = i >> 8;
        int h2 = i & 255;
        float wr = Wxy[(size_t)n * NH + h2];
        float wi = Wxy[(size_t)n * NH + NH2 + h2];
        __half2 hw = __floats2half2_rn(wr, wi);
        *(__half2*)&g_W[(size_t)n * NH + 2 * h2] = hw;
    }
}
__global__ void k_dummy() { if (threadIdx.x == 1024) g_dummy_sink = 1; }

// ========== kFS: warp-specialized fused Bu-HMMA producer + scan consumer ==========
// grid = 128 = (b4 0..63, chalf 0..1). 512 threads: warps 0-7 produce, 8-15 consume.
// Barriers: FULL_s = 1+s, EMPTY_s = 3+s (count 512); producer-internal = 5; consumer = 6.
#define SM_YS    0                       // 4 x 64 floats = 1024
#define SM_UHo   1056                    // 64 rows x 80B
#define SM_ULo   6176
#define SM_BU0   11296                   // 2 x (64 rows x 1040B); Bm staging overlays buf0
#define BU_PITCH 1040                    // 260 words == 4 mod 32: conflict-free D-frag STS
#define BU_SZ    (64 * BU_PITCH)         // 66560
#define SMEM_FS  (SM_BU0 + 2 * BU_SZ)    // 144416

__global__ void __launch_bounds__(512, 1)
kFS(const float* __restrict__ U,
    const float* __restrict__ lr_,
    const float* __restrict__ li_,
    const float* __restrict__ B,
    const float* __restrict__ y0,
    const float* __restrict__ Wyx,
    const float* __restrict__ byx) {
    extern __shared__ char smem[];
    const uint32_t sb = smem_u32(smem);
    const int tid   = threadIdx.x;
    const int chalf = blockIdx.x & 1;
    const int b4    = blockIdx.x >> 1;

    if (tid < 256) {
        // ===================== PRODUCER (warps 0-7) =====================
        const int ptid = tid;
        const int pwid = tid >> 5;
        const int lane = tid & 31;

        // ---- stage Bm into Bu-buffer-0 region (hi @ SM_BU0, lo @ +20480) ----
        {
            const int ch   = ptid;
            const int brow = chalf * 128 + (ch >> 1) + (ch & 1) * NH2;
            const float4* Bp = (const float4*)(B + (size_t)brow * NU);
            char* ph = smem + SM_BU0 + ch * 80;
            char* pl = smem + SM_BU0 + 20480 + ch * 80;
#pragma unroll
            for (int q = 0; q < 8; q += 2) {
                float4 w0 = Bp[q], w1 = Bp[q + 1];
                uint32_t h0, l0, h1, l1, h2v, l2v, h3, l3;
                split2h(w0.x, w0.y, h0, l0);
                split2h(w0.z, w0.w, h1, l1);
                split2h(w1.x, w1.y, h2v, l2v);
                split2h(w1.z, w1.w, h3, l3);
                *(uint4*)(ph + q * 8) = make_uint4(h0, h1, h2v, h3);
                *(uint4*)(pl + q * 8) = make_uint4(l0, l1, l2v, l3);
            }
        }
        NBAR_SYNC(5, 256);

        // ---- Bm frags register-resident (32 ch cols per warp) ----
        const int wmat    = lane >> 3;
        const int wrow_in = (lane & 7) + ((wmat >> 1) << 3);
        const int wkb     = wmat & 1;
        const uint32_t bOff = (uint32_t)(wrow_in * 80 + wkb * 16);
        uint32_t bmh[4][2][2], bml[4][2][2];
        {
            const uint32_t bmhB = sb + SM_BU0 + pwid * (32 * 80);
            const uint32_t bmlB = bmhB + 20480;
#pragma unroll
            for (int g = 0; g < 2; g++)
#pragma unroll
                for (int ks = 0; ks < 2; ks++) {
                    uint32_t r0, r1, r2, r3;
                    ldsm4(r0, r1, r2, r3, bmhB + g * (16 * 80) + bOff + ks * 32);
                    bmh[2 * g][ks][0] = r0; bmh[2 * g][ks][1] = r1;
                    bmh[2 * g + 1][ks][0] = r2; bmh[2 * g + 1][ks][1] = r3;
                    ldsm4(r0, r1, r2, r3, bmlB + g * (16 * 80) + bOff + ks * 32);
                    bml[2 * g][ks][0] = r0; bml[2 * g][ks][1] = r1;
                    bml[2 * g + 1][ks][0] = r2; bml[2 * g + 1][ks][1] = r3;
                }
            // HW-consume the ldsm results so the first bar truly orders them
            uint32_t chk = bmh[0][0][0] ^ bmh[0][1][0] ^ bmh[2][0][0] ^ bmh[2][1][0] ^
                           bml[0][0][0] ^ bml[0][1][0] ^ bml[2][0][0] ^ bml[2][1][0];
            if (chk == 0x9E3779B9u) *(volatile uint32_t*)(smem + 1024) = chk;
        }

        // ---- U prefetch: 2 slots/thread (rows r>>3, segs r&7 over 64 rows x 8 segs) ----
        auto uaddr = [&](int slot, int tile) {
            int row = slot >> 3, seg = slot & 7;
            int bb = b4 * 4 + (row >> 4);
            int t  = row & 15;
            return (const float4*)(U + ((size_t)(tile * TTI + t) * BATCH + bb) * NU + seg * 4);
        };
        float4 ua = *uaddr(ptid, 0);
        float4 ub = *uaddr(ptid + 256, 0);
        const int dr = lane >> 2;
        const int dc = (lane & 3) * 2;
        const uint32_t uOffBase = (uint32_t)((lane & 15) * 80 + (lane >> 4) * 16);

#pragma unroll 1
        for (int tile = 0; tile < NTIL; tile++) {
            const int s = tile & 1;
            if (tile >= 2) NBAR_SYNC(3 + s, 512);   // wait consumer freed Bu[s]
            NBAR_SYNC(5, 256);                      // U buffer free (prev ldsm consumed)
            {   // stage U tile (both slots)
                int row = ptid >> 3, seg = ptid & 7;
                uint32_t h0, l0, h1, l1;
                split2h(ua.x, ua.y, h0, l0);
                split2h(ua.z, ua.w, h1, l1);
                *(uint2*)(smem + SM_UHo + row * 80 + seg * 8) = make_uint2(h0, h1);
                *(uint2*)(smem + SM_ULo + row * 80 + seg * 8) = make_uint2(l0, l1);
                row += 32;
                split2h(ub.x, ub.y, h0, l0);
                split2h(ub.z, ub.w, h1, l1);
                *(uint2*)(smem + SM_UHo + row * 80 + seg * 8) = make_uint2(h0, h1);
                *(uint2*)(smem + SM_ULo + row * 80 + seg * 8) = make_uint2(l0, l1);
            }
            if (tile + 1 < NTIL) { ua = *uaddr(ptid, tile + 1); ub = *uaddr(ptid + 256, tile + 1); }
            NBAR_SYNC(5, 256);                      // U staged

            char* bu = smem + SM_BU0 + s * BU_SZ;
#pragma unroll
            for (int mt = 0; mt < 4; mt++) {        // 4 m-tiles of 16 rows (4b x 16t)
                uint32_t ah[2][4], al[2][4];
                const uint32_t uO = uOffBase + (uint32_t)(mt * 16 * 80);
                ldsm4(ah[0][0], ah[0][1], ah[0][2], ah[0][3], sb + SM_UHo + uO);
                ldsm4(ah[1][0], ah[1][1], ah[1][2], ah[1][3], sb + SM_UHo + uO + 32);
                ldsm4(al[0][0], al[0][1], al[0][2], al[0][3], sb + SM_ULo + uO);
                ldsm4(al[1][0], al[1][1], al[1][2], al[1][3], sb + SM_ULo + uO + 32);
                float acc[4][4];
#pragma unroll
                for (int nt = 0; nt < 4; nt++)
#pragma unroll
                    for (int e = 0; e < 4; e++) acc[nt][e] = 0.0f;
#pragma unroll
                for (int nt = 0; nt < 4; nt++)
#pragma unroll
                    for (int ks = 0; ks < 2; ks++) {
                        mma16816h(acc[nt], ah[ks], bmh[nt][ks]);
                        mma16816h(acc[nt], al[ks], bmh[nt][ks]);
                        mma16816h(acc[nt], ah[ks], bml[nt][ks]);
                    }
#pragma unroll
                for (int nt = 0; nt < 4; nt++) {
                    char* p = bu + (mt * 16 + dr) * BU_PITCH + (pwid * 32 + nt * 8 + dc) * 4;
                    *(float2*)p = make_float2(acc[nt][0], acc[nt][1]);
                    *(float2*)(p + 8 * BU_PITCH) = make_float2(acc[nt][2], acc[nt][3]);
                }
            }
            NBAR_ARRIVE(1 + s, 512);                // Bu[s] full
        }
    } else {
        // ===================== CONSUMER (warps 8-15) =====================
        const int ctid = tid - 256;
        const int bl0  = ctid >> 7;                 // 0/1; second lane = bl0+2
        const int p    = ctid & 127;
        const int h2   = chalf * 128 + p;
        const int b0   = b4 * 4 + bl0;
        const int b1   = b0 + 2;

        float* ys = (float*)(smem + SM_YS);
        ys[ctid] = y0[(b4 * 4 + (ctid >> 6)) * NY + (ctid & 63)];
        NBAR_SYNC(6, 256);

        // ---- x0 for both lanes (shared packed weights) ----
        float xr0, xi0, xr1, xi1;
        {
            unsigned long long accA = pack2(byx[h2], byx[h2 + NH2]);
            unsigned long long accB = accA;
            const float4* wr = (const float4*)(Wyx + (size_t)h2 * NY);
            const float4* wi = (const float4*)(Wyx + (size_t)(h2 + NH2) * NY);
            const float* ysb0 = ys + bl0 * NY;
            const float* ysb1 = ys + (bl0 + 2) * NY;
#pragma unroll
            for (int q = 0; q < NY / 4; q++) {
                float4 a = wr[q], c = wi[q];
                unsigned long long w0 = pack2(a.x, c.x), w1 = pack2(a.y, c.y);
                unsigned long long w2 = pack2(a.z, c.z), w3 = pack2(a.w, c.w);
                accA = fma2(w0, dup2(ysb0[4 * q + 0]), accA);
                accA = fma2(w1, dup2(ysb0[4 * q + 1]), accA);
                accA = fma2(w2, dup2(ysb0[4 * q + 2]), accA);
                accA = fma2(w3, dup2(ysb0[4 * q + 3]), accA);
                accB = fma2(w0, dup2(ysb1[4 * q + 0]), accB);
                accB = fma2(w1, dup2(ysb1[4 * q + 1]), accB);
                accB = fma2(w2, dup2(ysb1[4 * q + 2]), accB);
                accB = fma2(w3, dup2(ysb1[4 * q + 3]), accB);
            }
            unpack2(accA, xr0, xi0);
            unpack2(accB, xr1, xi1);
        }
        store_f16(xr0, xi0, (size_t)b0 * NH + 2 * h2);
        store_f16(xr1, xi1, (size_t)b1 * NH + 2 * h2);
        const float lam_r = lr_[h2];
        const float lam_i = li_[h2];
        const size_t st = (size_t)BATCH * NH;

#pragma unroll 1
        for (int tile = 0; tile < NTIL; tile++) {
            const int s = tile & 1;
            NBAR_SYNC(1 + s, 512);                  // wait Bu[s] full
            const char* bu = smem + SM_BU0 + s * BU_SZ;
            const char* q0 = bu + (bl0 * 16) * BU_PITCH + p * 8;
            const char* q1 = bu + ((bl0 + 2) * 16) * BU_PITCH + p * 8;
            const int t0 = tile * TTI;
#pragma unroll
            for (int j0 = 0; j0 < TTI; j0 += 4) {
                float2 c00 = *(const float2*)(q0 + (j0 + 0) * BU_PITCH);
                float2 c01 = *(const float2*)(q0 + (j0 + 1) * BU_PITCH);
                float2 c02 = *(const float2*)(q0 + (j0 + 2) * BU_PITCH);
                float2 c03 = *(const float2*)(q0 + (j0 + 3) * BU_PITCH);
                float2 c10 = *(const float2*)(q1 + (j0 + 0) * BU_PITCH);
                float2 c11 = *(const float2*)(q1 + (j0 + 1) * BU_PITCH);
                float2 c12 = *(const float2*)(q1 + (j0 + 2) * BU_PITCH);
                float2 c13 = *(const float2*)(q1 + (j0 + 3) * BU_PITCH);
                size_t ob0 = ((size_t)(t0 + j0 + 1) * BATCH + b0) * NH + 2 * h2;
                size_t ob1 = ((size_t)(t0 + j0 + 1) * BATCH + b1) * NH + 2 * h2;
                float nr, ni;
                nr = fmaf(lam_r, xr0, fmaf(-lam_i, xi0, c00.x));
                ni = fmaf(lam_i, xr0, fmaf(lam_r, xi0, c00.y));
                xr0 = nr; xi0 = ni; store_f16(xr0, xi0, ob0);
                nr = fmaf(lam_r, xr1, fmaf(-lam_i, xi1, c10.x));
                ni = fmaf(lam_i, xr1, fmaf(lam_r, xi1, c10.y));
                xr1 = nr; xi1 = ni; store_f16(xr1, xi1, ob1);
                nr = fmaf(lam_r, xr0, fmaf(-lam_i, xi0, c01.x));
                ni = fmaf(lam_i, xr0, fmaf(lam_r, xi0, c01.y));
                xr0 = nr; xi0 = ni; store_f16(xr0, xi0, ob0 + st);
                nr = fmaf(lam_r, xr1, fmaf(-lam_i, xi1, c11.x));
                ni = fmaf(lam_i, xr1, fmaf(lam_r, xi1, c11.y));
                xr1 = nr; xi1 = ni; store_f16(xr1, xi1, ob1 + st);
                nr = fmaf(lam_r, xr0, fmaf(-lam_i, xi0, c02.x));
                ni = fmaf(lam_i, xr0, fmaf(lam_r, xi0, c02.y));
                xr0 = nr; xi0 = ni; store_f16(xr0, xi0, ob0 + 2 * st);
                nr = fmaf(lam_r, xr1, fmaf(-lam_i, xi1, c12.x));
                ni = fmaf(lam_i, xr1, fmaf(lam_r, xi1, c12.y));
                xr1 = nr; xi1 = ni; store_f16(xr1, xi1, ob1 + 2 * st);
                nr = fmaf(lam_r, xr0, fmaf(-lam_i, xi0, c03.x));
                ni = fmaf(lam_i, xr0, fmaf(lam_r, xi0, c03.y));
                xr0 = nr; xi0 = ni; store_f16(xr0, xi0, ob0 + 3 * st);
                nr = fmaf(lam_r, xr1, fmaf(-lam_i, xi1, c13.x));
                ni = fmaf(lam_i, xr1, fmaf(lam_r, xi1, c13.y));
                xr1 = nr; xi1 = ni; store_f16(xr1, xi1, ob1 + 3 * st);
            }
            if (tile < NTIL - 2) NBAR_ARRIVE(3 + s, 512);   // Bu[s] empty
        }
    }
}

// ========== K3: HMMA fp16 single-product GEMM (unchanged from R12) ==========
#define KC        32
#define NCH       16
#define A_STRIDE  80
#define SM_BIAS   0
#define STAGE_SZ  25600
#define SM_A(s)   (512 + (s) * STAGE_SZ)
#define SM_W3(s)  (SM_A(s) + 20480)
#define SMEM_K3   (512 + 2 * STAGE_SZ)

__global__ void __launch_bounds__(256, 2)
k3_mma(const float* __restrict__ bias, float* __restrict__ Y) {
    extern __shared__ char smem[];
    const uint32_t sb = smem_u32(smem);
    const int tid  = threadIdx.x;
    const int wid  = tid >> 5;
    const int lane = tid & 31;
    const int t    = blockIdx.x;

    float* s_bias = (float*)(smem + SM_BIAS);
    if (tid < NY) s_bias[tid] = bias[tid];

    const size_t Abase = (size_t)t * BATCH * NH;
    const int lrow = tid >> 2;
    const int lseg = tid & 3;

    auto stage_load = [&](int c) {
        const int s = c & 1;
        const __half* af = g_Xf + Abase + c * KC;
#pragma unroll
        for (int p = 0; p < 4; p++) {
            int row = p * 64 + lrow;
            uint32_t d = row * A_STRIDE + lseg * 16;
            cpa16(sb + SM_A(s) + d, af + (size_t)row * NH + lseg * 8);
        }
        {
            const __half* w = g_W + c * KC;
            int row = lrow;
            uint32_t d = row * A_STRIDE + lseg * 16;
            cpa16(sb + SM_W3(s) + d, w + (size_t)row * NH + lseg * 8);
        }
        cp_commit();
    };

    float acc[2][8][4];
#pragma unroll
    for (int mt = 0; mt < 2; mt++)
#pragma unroll
        for (int nt = 0; nt < 8; nt++)
#pragma unroll
            for (int e = 0; e < 4; e++) acc[mt][nt][e] = 0.0f;

    const int arow = wid * 32 + (lane & 15);
    const int akb  = (lane >> 4) * 16;
    const uint32_t aOff = arow * A_STRIDE + akb;
    const int wmat = lane >> 3;
    const int wrow_in = (lane & 7) + ((wmat >> 1) << 3);
    const int wkb  = (wmat & 1) * 16;
    const uint32_t wOff = wrow_in * A_STRIDE + wkb;

    stage_load(0);

#pragma unroll 1
    for (int c = 0; c < NCH; c++) {
        const int s = c & 1;
        if (c + 1 < NCH) { stage_load(c + 1); cp_wait<1>(); }
        else             { cp_wait<0>(); }
        __syncthreads();

#pragma unroll
        for (int ks = 0; ks < 2; ks++) {
            const uint32_t ko = ks * 32;
            uint32_t af[2][4];
#pragma unroll
            for (int mt = 0; mt < 2; mt++) {
                uint32_t aA = sb + SM_A(s) + aOff + mt * (16 * A_STRIDE) + ko;
                ldsm4(af[mt][0], af[mt][1], af[mt][2], af[mt][3], aA);
            }
            uint32_t whf[8][2];
#pragma unroll
            for (int g = 0; g < 4; g++) {
                uint32_t r0, r1, r2, r3;
                uint32_t wA = sb + SM_W3(s) + wOff + g * (16 * A_STRIDE) + ko;
                ldsm4(r0, r1, r2, r3, wA);
                whf[2 * g][0] = r0; whf[2 * g][1] = r1;
                whf[2 * g + 1][0] = r2; whf[2 * g + 1][1] = r3;
            }
#pragma unroll
            for (int mt = 0; mt < 2; mt++)
#pragma unroll
                for (int nt = 0; nt < 8; nt++)
                    mma16816h(acc[mt][nt], af[mt], whf[nt]);
        }
        __syncthreads();
    }

    const int r0base = wid * 32 + (lane >> 2);
    const int coff   = (lane & 3) * 2;
#pragma unroll
    for (int mt = 0; mt < 2; mt++) {
#pragma unroll
        for (int nt = 0; nt < 8; nt++) {
            const int cb = nt * 8 + coff;
            const float b0 = s_bias[cb], b1 = s_bias[cb + 1];
            const int ra = r0base + mt * 16;
            float* y0p = Y + ((size_t)t * BATCH + ra) * NY + cb;
            float* y1p = Y + ((size_t)t * BATCH + ra + 8) * NY + cb;
            *(float2*)y0p = make_float2(acc[mt][nt][0] + b0, acc[mt][nt][1] + b1);
            *(float2*)y1p = make_float2(acc[mt][nt][2] + b0, acc[mt][nt][3] + b1);
        }
    }
}

extern "C" void kernel_launch(void* const* d_in, const int* in_sizes, int n_in,
                              void* d_out, int out_size) {
    (void)in_sizes; (void)n_in; (void)out_size;
    const float* y0  = (const float*)d_in[0];
    const float* U   = (const float*)d_in[1];
    const float* lr  = (const float*)d_in[2];
    const float* li  = (const float*)d_in[3];
    const float* B   = (const float*)d_in[4];
    const float* Wyx = (const float*)d_in[5];
    const float* byx = (const float*)d_in[6];
    const float* Wxy = (const float*)d_in[7];
    const float* bxy = (const float*)d_in[8];
    float* Y = (float*)d_out;

    static bool attr_done = false;
    if (!attr_done) {
        cudaFuncSetAttribute(k3_mma, cudaFuncAttributeMaxDynamicSharedMemorySize, SMEM_K3);
        cudaFuncSetAttribute(kFS, cudaFuncAttributeMaxDynamicSharedMemorySize, SMEM_FS);
        attr_done = true;
    }

    // profiled launch = index 3 = kFS
    k0_wsplit<<<32, 256>>>(Wxy);
    k_dummy<<<1, 32>>>();
    k_dummy<<<1, 32>>>();
    kFS<<<128, 512, SMEM_FS>>>(U, lr, li, B, y0, Wyx, byx);
    k3_mma<<<T_STEPS + 1, 256, SMEM_K3>>>(bxy, Y);
}